// round 2
// baseline (speedup 1.0000x reference)
#include <cuda_runtime.h>

#define BB   8
#define CC   16
#define HH   128
#define WW   128
#define PP   16384
#define KN   16
#define CK   144
#define IMG  (CC*HH*WW)      // 262144 = 2^18
#define NT   256
#define PAD  148             // padded row stride (floats)

// Flag: 1 if hash_idx buffer is int64 (high 32-bit words all zero), 0 if int32.
__device__ int g_idx_is64;

// Probe: sample 32 odd 32-bit words within the first N words (safe for both
// int32 [N words] and int64 [2N words] layouts). int64 => high words == 0.
__global__ void probe_idx_kernel(const unsigned* __restrict__ h32) {
    // positions 2*(t*36000)+1 <= 2*1116000+1 < N = 2359296
    unsigned v = h32[2u * (threadIdx.x * 36000u) + 1u];
    int all0 = __all_sync(0xFFFFFFFFu, v == 0u);
    if (threadIdx.x == 0) g_idx_is64 = all0;
}

__global__ __launch_bounds__(NT) void abc2d_kernel(
    const float* __restrict__ x,
    const float* __restrict__ weights,
    const unsigned* __restrict__ hidx32,
    float* __restrict__ out)
{
    __shared__ __align__(16) int   sidx[CK];
    __shared__ __align__(16) float patchB[BB][PAD];   // [b][c]
    __shared__ __align__(16) float wsm[KN][PAD];      // [k][c]

    const int p = blockIdx.x;
    const int t = threadIdx.x;

    // ---- stage hash indices (dtype-robust: int32 or low word of int64) ----
    if (t < CK) {
        long long e = (long long)p * CK + t;
        unsigned w = g_idx_is64 ? hidx32[2 * e] : hidx32[e];
        sidx[t] = (int)(w & (IMG - 1));   // mask to valid range (IMG is 2^18)
    }
    __syncthreads();

    // ---- gather patches: 1152 scattered 4B loads, 4-5 independent per thread ----
    {
        #pragma unroll
        for (int r = 0; r < 4; r++) {
            int e = t + r * NT;          // e in [0,1024)
            int b = e & 7;
            int c = e >> 3;
            patchB[b][c] = __ldg(&x[sidx[c] + b * IMG]);
        }
        if (t < (BB * CK - 4 * NT)) {    // remaining 128
            int e = t + 4 * NT;
            int b = e & 7;
            int c = e >> 3;
            patchB[b][c] = __ldg(&x[sidx[c] + b * IMG]);
        }
    }

    // ---- stage weight tile [16][144] via coalesced float4, evict-first ----
    {
        const float4* wp = (const float4*)(weights + (size_t)p * (KN * CK));
        #pragma unroll
        for (int r = 0; r < 2; r++) {
            int i = t + r * NT;          // i in [0,512)
            float4 v = __ldcs(&wp[i]);
            int k = i / 36;              // 36 float4 per k-row
            int c = (i - k * 36) * 4;
            *(float4*)&wsm[k][c] = v;
        }
        if (t < (KN * CK / 4 - 2 * NT)) { // remaining 64
            int i = t + 2 * NT;
            float4 v = __ldcs(&wp[i]);
            int k = i / 36;
            int c = (i - k * 36) * 4;
            *(float4*)&wsm[k][c] = v;
        }
    }
    __syncthreads();

    // ---- compute: thread t<128 owns output (k,b) ----
    if (t < KN * BB) {
        const int k = t >> 3;
        const int b = t & 7;
        float acc = 0.f;
        #pragma unroll
        for (int c4 = 0; c4 < CK / 4; c4++) {
            float4 w4 = *(const float4*)&wsm[k][c4 * 4];
            float4 p4 = *(const float4*)&patchB[b][c4 * 4];
            acc += w4.x * p4.x;
            acc += w4.y * p4.y;
            acc += w4.z * p4.z;
            acc += w4.w * p4.w;
        }
        // out[b, k, p] with P = 16384
        out[((b * KN + k) << 14) + p] = acc;
    }
}

extern "C" void kernel_launch(void* const* d_in, const int* in_sizes, int n_in,
                              void* d_out, int out_size) {
    const float*    x   = (const float*)d_in[0];
    const float*    w   = (const float*)d_in[1];
    const unsigned* hid = (const unsigned*)d_in[2];
    float*          out = (float*)d_out;
    (void)in_sizes; (void)n_in; (void)out_size;

    probe_idx_kernel<<<1, 32>>>(hid);
    abc2d_kernel<<<PP, NT>>>(x, w, hid, out);
}

// round 3
// speedup vs baseline: 1.4763x; 1.4763x over previous
#include <cuda_runtime.h>

#define BB   8
#define CC   16
#define HH   128
#define WW   128
#define PP   16384
#define KN   16
#define CK   144
#define IMG  (CC*HH*WW)      // 262144 = 2^18
#define NT   256
#define PAD  148

// 8 MB scratch: x transposed to batch-innermost  x_t[i][b] = x[b][i]
__device__ __align__(32) float g_xt[IMG * BB];

// Flag: 1 if hash_idx buffer is int64 (high 32-bit words all zero), 0 if int32.
__device__ int g_idx_is64;

__global__ void probe_idx_kernel(const unsigned* __restrict__ h32) {
    unsigned v = h32[2u * (threadIdx.x * 36000u) + 1u];
    int all0 = __all_sync(0xFFFFFFFFu, v == 0u);
    if (threadIdx.x == 0) g_idx_is64 = all0;
}

// Transpose x [B][IMG] -> g_xt [IMG][B]. Coalesced reads (contiguous i per b)
// and coalesced writes (warp covers 1024 contiguous bytes via STG.128).
__global__ __launch_bounds__(NT) void transpose_kernel(const float* __restrict__ x)
{
    int i = blockIdx.x * NT + threadIdx.x;   // i in [0, IMG)
    float v[BB];
    #pragma unroll
    for (int b = 0; b < BB; b++)
        v[b] = __ldg(&x[b * IMG + i]);
    float4* dst = (float4*)&g_xt[(size_t)i * BB];
    dst[0] = make_float4(v[0], v[1], v[2], v[3]);
    dst[1] = make_float4(v[4], v[5], v[6], v[7]);
}

__global__ __launch_bounds__(NT) void abc2d_kernel(
    const float* __restrict__ weights,
    const unsigned* __restrict__ hidx32,
    float* __restrict__ out)
{
    __shared__ __align__(16) int   sidx[CK];
    __shared__ __align__(16) float patchT[CK][BB];    // [c][b], rows 32B
    __shared__ __align__(16) float wsm[KN][PAD];      // [k][c]

    const int p = blockIdx.x;
    const int t = threadIdx.x;

    // ---- stage hash indices (int32 or low word of int64) ----
    if (t < CK) {
        long long e = (long long)p * CK + t;
        unsigned w = g_idx_is64 ? hidx32[2 * e] : hidx32[e];
        sidx[t] = (int)(w & (IMG - 1));
    }
    __syncthreads();

    // ---- gather: 288 float4 lanes (2 per c) pull all 8 batch values per tap ----
    {
        int e = t;                       // e = c*2 + half
        int c = e >> 1, half = e & 1;
        float4 v = __ldg((const float4*)&g_xt[(size_t)sidx[c] * BB + half * 4]);
        *(float4*)&patchT[c][half * 4] = v;
        if (t < 2 * CK - NT) {           // remaining 32
            int e2 = t + NT;
            int c2 = e2 >> 1, h2 = e2 & 1;
            float4 v2 = __ldg((const float4*)&g_xt[(size_t)sidx[c2] * BB + h2 * 4]);
            *(float4*)&patchT[c2][h2 * 4] = v2;
        }
    }

    // ---- stage weight tile [16][144] via coalesced float4, evict-first ----
    {
        const float4* wp = (const float4*)(weights + (size_t)p * (KN * CK));
        #pragma unroll
        for (int r = 0; r < 2; r++) {
            int i = t + r * NT;          // i in [0,512)
            float4 v = __ldcs(&wp[i]);
            int k = i / 36;
            int c = (i - k * 36) * 4;
            *(float4*)&wsm[k][c] = v;
        }
        if (t < (KN * CK / 4 - 2 * NT)) { // remaining 64
            int i = t + 2 * NT;
            float4 v = __ldcs(&wp[i]);
            int k = i / 36;
            int c = (i - k * 36) * 4;
            *(float4*)&wsm[k][c] = v;
        }
    }
    __syncthreads();

    // ---- compute: thread t<128 owns output (k,b); warp = 4k x 8b ----
    if (t < KN * BB) {
        const int k = t >> 3;
        const int b = t & 7;
        float acc = 0.f;
        #pragma unroll
        for (int c4 = 0; c4 < CK / 4; c4++) {
            float4 w4 = *(const float4*)&wsm[k][c4 * 4];
            acc += w4.x * patchT[c4 * 4 + 0][b];
            acc += w4.y * patchT[c4 * 4 + 1][b];
            acc += w4.z * patchT[c4 * 4 + 2][b];
            acc += w4.w * patchT[c4 * 4 + 3][b];
        }
        out[((b * KN + k) << 14) + p] = acc;   // out[b,k,p], P=2^14
    }
}

extern "C" void kernel_launch(void* const* d_in, const int* in_sizes, int n_in,
                              void* d_out, int out_size) {
    const float*    x   = (const float*)d_in[0];
    const float*    w   = (const float*)d_in[1];
    const unsigned* hid = (const unsigned*)d_in[2];
    float*          out = (float*)d_out;
    (void)in_sizes; (void)n_in; (void)out_size;

    probe_idx_kernel<<<1, 32>>>(hid);
    transpose_kernel<<<IMG / NT, NT>>>(x);
    abc2d_kernel<<<PP, NT>>>(w, hid, out);
}